// round 2
// baseline (speedup 1.0000x reference)
#include <cuda_runtime.h>
#include <cstdint>

#define N_ANCH   100800
#define D_COLS   117
#define NC       80
#define NM       32
#define TOPK     4096
#define MAX_DET  300
#define CONF_T   0.25f
#define IOU_T    0.45f
#define CAND_CAP 8192
#define EMAX     (1 << 20)      // edge buffer capacity

// ---------------- scratch (static __device__ — no allocation) ----------------
__device__ float              g_score[N_ANCH];
__device__ float              g_cls[N_ANCH];
__device__ unsigned int       g_hist[65536];
__device__ unsigned int       g_chunk[64];
__device__ unsigned int       g_thresh_bucket;
__device__ unsigned int       g_ncand;
__device__ unsigned long long g_cand[CAND_CAP];
__device__ int                g_top_idx[TOPK];
__device__ float              g_top_s[TOPK];
__device__ float              g_by1[TOPK], g_bx1[TOPK], g_by2[TOPK], g_bx2[TOPK], g_bar[TOPK];
__device__ unsigned int       g_nedge;
__device__ unsigned int       g_ecnt[TOPK];
__device__ unsigned int       g_efill[TOPK];
__device__ unsigned int       g_eoff[TOPK];
__device__ unsigned int       g_etot;
__device__ unsigned int       g_eraw[EMAX];
__device__ unsigned int       g_edges[EMAX];
__device__ int                g_out_pos[MAX_DET];
__device__ unsigned char      g_out_keep[MAX_DET];

// ---------------- helpers ----------------
__device__ __forceinline__ unsigned int f2key(float f) {
    unsigned int b = __float_as_uint(f);
    return b ^ ((b >> 31) ? 0xFFFFFFFFu : 0x80000000u);
}
__device__ __forceinline__ float key2f(unsigned int k) {
    unsigned int b = (k & 0x80000000u) ? (k ^ 0x80000000u) : ~k;
    return __uint_as_float(b);
}

// ---------------- k0: zero scratch ----------------
__global__ void k_zero() {
    int i = blockIdx.x * blockDim.x + threadIdx.x;          // 65536 threads
    g_hist[i] = 0u;
    if (i < TOPK) { g_ecnt[i] = 0u; g_efill[i] = 0u; }
    if (i == 0)   { g_ncand = 0u; g_nedge = 0u; }
}

// ---------------- k1: per-anchor score/class + histogram (warp per anchor) ---
__global__ void k_score(const float* __restrict__ x) {
    int warp = (blockIdx.x * blockDim.x + threadIdx.x) >> 5;
    int lane = threadIdx.x & 31;
    if (warp >= N_ANCH) return;
    const float* row = x + (size_t)warp * D_COLS;
    float obj = row[4];

    float best = -1.0f; int bc = NC;
#pragma unroll
    for (int k = 0; k < 3; k++) {
        int c = lane + 32 * k;
        if (c < NC) {
            float v = __fmul_rn(row[5 + c], obj);
            if (v > best) { best = v; bc = c; }
        }
    }
#pragma unroll
    for (int off = 16; off; off >>= 1) {
        float ov = __shfl_down_sync(0xFFFFFFFFu, best, off);
        int   oc = __shfl_down_sync(0xFFFFFFFFu, bc,   off);
        if (ov > best || (ov == best && oc < bc)) { best = ov; bc = oc; }
    }
    if (lane == 0) {
        float s = (obj > CONF_T) ? best : -1.0f;
        g_score[warp] = s;
        g_cls[warp]   = (float)bc;
        atomicAdd(&g_hist[f2key(s) >> 16], 1u);
    }
}

// ---------------- k2a: coalesced 1024-bucket chunk sums ----------------------
__global__ void k_chunk() {
    __shared__ unsigned int red[256];
    int b = blockIdx.x, t = threadIdx.x;
    unsigned int s = 0;
#pragma unroll
    for (int k = 0; k < 4; k++) s += g_hist[b * 1024 + k * 256 + t];
    red[t] = s;
    __syncthreads();
    for (int off = 128; off; off >>= 1) {
        if (t < off) red[t] += red[t + off];
        __syncthreads();
    }
    if (t == 0) g_chunk[b] = red[0];
}

// ---------------- k2b: threshold bucket -------------------------------------
__global__ void k_thresh2() {
    __shared__ unsigned int suf[1024];
    __shared__ unsigned int csum[64];
    __shared__ int          s_c;
    __shared__ unsigned int s_rem;
    int t = threadIdx.x;
    if (t < 64) csum[t] = g_chunk[t];
    __syncthreads();
    if (t == 0) {
        unsigned int cum = 0; int c = 0; unsigned int rem = TOPK;
        for (int b = 63; b >= 0; b--) {
            if (cum + csum[b] >= TOPK) { c = b; rem = TOPK - cum; break; }
            cum += csum[b];
        }
        s_c = c; s_rem = rem;
    }
    __syncthreads();
    int c = s_c;
    suf[t] = g_hist[c * 1024 + t];
    __syncthreads();
    for (int off = 1; off < 1024; off <<= 1) {
        unsigned int v = (t + off < 1024) ? suf[t + off] : 0u;
        __syncthreads();
        suf[t] += v;
        __syncthreads();
    }
    unsigned int rem = s_rem;
    if (suf[t] >= rem && (t == 1023 || suf[t + 1] < rem))
        g_thresh_bucket = (unsigned int)(c * 1024 + t);
}

// ---------------- k3: compact candidates ----------------
__global__ void k_compact() {
    int i = blockIdx.x * blockDim.x + threadIdx.x;
    if (i >= N_ANCH) return;
    unsigned int k = f2key(g_score[i]);
    if ((k >> 16) >= g_thresh_bucket) {
        unsigned int pos = atomicAdd(&g_ncand, 1u);
        if (pos < CAND_CAP)
            g_cand[pos] = ((unsigned long long)k << 32) | (unsigned int)(~i);
    }
}

// ---------------- k4: rank candidates -> sorted top-4096 ----------------
__global__ void k_rank() {
    __shared__ unsigned long long tile[256];
    int i = blockIdx.x * 256 + threadIdx.x;
    unsigned int n = g_ncand; if (n > CAND_CAP) n = CAND_CAP;
    unsigned long long my = (i < (int)n) ? g_cand[i] : 0ULL;
    int rank = 0;
    for (unsigned int base = 0; base < n; base += 256) {
        unsigned int idx = base + threadIdx.x;
        tile[threadIdx.x] = (idx < n) ? g_cand[idx] : 0ULL;
        __syncthreads();
        unsigned int lim = (n - base < 256u) ? (n - base) : 256u;
        for (unsigned int k = 0; k < lim; k++) rank += (tile[k] > my);
        __syncthreads();
    }
    if (i < (int)n && rank < TOPK) {
        g_top_s[rank]   = key2f((unsigned int)(my >> 32));
        g_top_idx[rank] = (int)(~(unsigned int)my);
    }
}

// ---------------- k5: gather boxes + areas of the top-4096 -------------------
__global__ void k_gather(const float* __restrict__ x) {
    int i = blockIdx.x * blockDim.x + threadIdx.x;
    if (i >= TOPK) return;
    const float* row = x + (size_t)g_top_idx[i] * D_COLS;
    float xc = row[0], yc = row[1], w = row[2], h = row[3];
    float hh = __fmul_rn(h, 0.5f), hw = __fmul_rn(w, 0.5f);
    float y1 = __fsub_rn(yc, hh), x1 = __fsub_rn(xc, hw);
    float y2 = __fadd_rn(yc, hh), x2 = __fadd_rn(xc, hw);
    g_by1[i] = y1; g_bx1[i] = x1; g_by2[i] = y2; g_bx2[i] = x2;
    g_bar[i] = __fmul_rn(__fsub_rn(y2, y1), __fsub_rn(x2, x1));
}

// ---------------- k6: sparse suppression edges (chip-parallel) ---------------
// warp g handles rows rg*32..rg*32+31 vs cols w*32..w*32+31 (upper triangle)
__global__ void k_edges() {
    __shared__ float cy1[4][32], cx1[4][32], cy2[4][32], cx2[4][32], car[4][32];
    int wid  = threadIdx.x >> 5;
    int lane = threadIdx.x & 31;
    int g    = blockIdx.x * 4 + wid;            // 0..16383
    int rg   = g >> 7;
    int w    = g & 127;
    if (w < rg) return;

    int j0 = w << 5;
    int jj = j0 + lane;
    cy1[wid][lane] = g_by1[jj]; cx1[wid][lane] = g_bx1[jj];
    cy2[wid][lane] = g_by2[jj]; cx2[wid][lane] = g_bx2[jj];
    car[wid][lane] = g_bar[jj];
    __syncwarp();

    int   i   = (rg << 5) | lane;
    float ry1 = g_by1[i], rx1 = g_bx1[i], ry2 = g_by2[i], rx2 = g_bx2[i];
    float rar = g_bar[i];
    bool  diag = (w == rg);

#pragma unroll 4
    for (int k = 0; k < 32; k++) {
        if (diag && k <= lane) continue;
        float yy1 = fmaxf(ry1, cy1[wid][k]);
        float xx1 = fmaxf(rx1, cx1[wid][k]);
        float yy2 = fminf(ry2, cy2[wid][k]);
        float xx2 = fminf(rx2, cx2[wid][k]);
        float dh  = fmaxf(__fsub_rn(yy2, yy1), 0.0f);
        float dw  = fmaxf(__fsub_rn(xx2, xx1), 0.0f);
        float it  = __fmul_rn(dh, dw);
        if (it > 0.0f) {
            float un  = __fsub_rn(__fadd_rn(rar, car[wid][k]), it);
            float unc = fmaxf(un, 1e-9f);
            float c   = __fmul_rn(IOU_T, unc);
            bool  sup;
            if (fabsf(__fsub_rn(it, c)) > 1e-4f * c) {
                sup = (it > c);                                // far from boundary
            } else {
                sup = (__fdiv_rn(it, unc) > IOU_T);            // exact ref rounding
            }
            if (sup) {
                unsigned int pos = atomicAdd(&g_nedge, 1u);
                if (pos < EMAX) {
                    g_eraw[pos] = ((unsigned int)i << 12) | (unsigned int)(j0 + k);
                    atomicAdd(&g_ecnt[i], 1u);
                }
            }
        }
    }
}

// ---------------- k7: exclusive scan of per-row edge counts ------------------
__global__ void k_escan() {
    __shared__ unsigned int sc[1024];
    int t = threadIdx.x;
    unsigned int a0 = g_ecnt[4 * t + 0], a1 = g_ecnt[4 * t + 1];
    unsigned int a2 = g_ecnt[4 * t + 2], a3 = g_ecnt[4 * t + 3];
    unsigned int s  = a0 + a1 + a2 + a3;
    sc[t] = s;
    __syncthreads();
    for (int off = 1; off < 1024; off <<= 1) {
        unsigned int v = (t >= off) ? sc[t - off] : 0u;
        __syncthreads();
        sc[t] += v;
        __syncthreads();
    }
    unsigned int base = t ? sc[t - 1] : 0u;
    g_eoff[4 * t + 0] = base;
    g_eoff[4 * t + 1] = base + a0;
    g_eoff[4 * t + 2] = base + a0 + a1;
    g_eoff[4 * t + 3] = base + a0 + a1 + a2;
    if (t == 1023) g_etot = sc[1023];
}

// ---------------- k8: scatter edges into i-sorted order ---------------------
__global__ void k_escatter() {
    unsigned int idx = blockIdx.x * blockDim.x + threadIdx.x;
    unsigned int n = g_nedge; if (n > EMAX) n = EMAX;
    if (idx >= n) return;
    unsigned int code = g_eraw[idx];
    unsigned int i = code >> 12;
    unsigned int pos = atomicAdd(&g_efill[i], 1u);
    g_edges[g_eoff[i] + pos] = code;
}

// ---------------- k9: sequential greedy resolve over sparse edges -----------
#define RTILE 8192
__global__ void __launch_bounds__(1024, 1) k_resolve() {
    __shared__ unsigned int remv[128];
    __shared__ unsigned int tile[RTILE];
    int t = threadIdx.x;

    if (t < 128) {                 // keep0: removed iff score <= -0.5
        unsigned int wbits = 0;
        for (int b = 0; b < 32; b++)
            if (!(g_top_s[t * 32 + b] > -0.5f)) wbits |= 1u << b;
        remv[t] = wbits;
    }
    __syncthreads();

    unsigned int E = g_etot;
    for (unsigned int base = 0; base < E; base += RTILE) {
        unsigned int m = E - base; if (m > RTILE) m = RTILE;
        for (unsigned int idx = t; idx < m; idx += 1024) tile[idx] = g_edges[base + idx];
        __syncthreads();
        if (t == 0) {
            for (unsigned int e = 0; e < m; e++) {
                unsigned int code = tile[e];
                unsigned int i = code >> 12;
                unsigned int j = code & 4095u;
                if (!((remv[i >> 5] >> (i & 31)) & 1u))
                    remv[j >> 5] |= 1u << (j & 31);
            }
        }
        __syncthreads();
    }

    if (t == 0) {                  // final top-300 positions (kept first, then pad)
        int cnt = 0;
        for (int w = 0; w < 128 && cnt < MAX_DET; w++) {
            unsigned int alive = ~remv[w];
            while (alive && cnt < MAX_DET) {
                int b = __ffs(alive) - 1; alive &= alive - 1;
                g_out_pos[cnt] = (w << 5) | b; g_out_keep[cnt] = 1; cnt++;
            }
        }
        for (int w = 0; w < 128 && cnt < MAX_DET; w++) {
            unsigned int dead = remv[w];
            while (dead && cnt < MAX_DET) {
                int b = __ffs(dead) - 1; dead &= dead - 1;
                g_out_pos[cnt] = (w << 5) | b; g_out_keep[cnt] = 0; cnt++;
            }
        }
    }
}

// ---------------- k10: final gather -> d_out (warp per detection) ------------
__global__ void k_out(const float* __restrict__ x, float* __restrict__ out) {
    int warp = (blockIdx.x * blockDim.x + threadIdx.x) >> 5;
    int lane = threadIdx.x & 31;
    if (warp >= MAX_DET) return;
    int pos = g_out_pos[warp];
    int a   = g_top_idx[pos];
    const float* row = x + (size_t)a * D_COLS;
    if (lane == 0) {
        float xc = row[0], yc = row[1], w = row[2], h = row[3];
        float hh = __fmul_rn(h, 0.5f), hw = __fmul_rn(w, 0.5f);
        out[warp * 4 + 0] = __fsub_rn(yc, hh);
        out[warp * 4 + 1] = __fsub_rn(xc, hw);
        out[warp * 4 + 2] = __fadd_rn(yc, hh);
        out[warp * 4 + 3] = __fadd_rn(xc, hw);
        out[MAX_DET * 4 + warp] = g_cls[a];
        out[MAX_DET * 5 + warp] = g_out_keep[warp] ? g_top_s[pos] : -1.0f;
    }
    out[MAX_DET * 6 + warp * NM + lane] = row[5 + NC + lane];
}

// ---------------- launch ----------------
extern "C" void kernel_launch(void* const* d_in, const int* in_sizes, int n_in,
                              void* d_out, int out_size) {
    const float* x = (const float*)d_in[0];
    float* out = (float*)d_out;

    k_zero    <<<64, 1024>>>();
    k_score   <<<(N_ANCH * 32 + 255) / 256, 256>>>(x);
    k_chunk   <<<64, 256>>>();
    k_thresh2 <<<1, 1024>>>();
    k_compact <<<(N_ANCH + 255) / 256, 256>>>();
    k_rank    <<<CAND_CAP / 256, 256>>>();
    k_gather  <<<TOPK / 256, 256>>>(x);
    k_edges   <<<4096, 128>>>();
    k_escan   <<<1, 1024>>>();
    k_escatter<<<EMAX / 256, 256>>>();
    k_resolve <<<1, 1024>>>();
    k_out     <<<(MAX_DET * 32 + 255) / 256, 256>>>(x, out);
}

// round 3
// speedup vs baseline: 26.6868x; 26.6868x over previous
#include <cuda_runtime.h>
#include <cstdint>

#define N_ANCH   100800
#define D_COLS   117
#define NC       80
#define NM       32
#define TOPK     4096
#define MAX_DET  300
#define CONF_T   0.25f
#define IOU_T    0.45f
#define CAND_CAP 8192
#define NWORDS   128            // TOPK/32

// ---------------- scratch (static __device__ — no allocation) ----------------
__device__ float              g_score[N_ANCH];
__device__ float              g_cls[N_ANCH];
__device__ unsigned int       g_hist[65536];
__device__ unsigned int       g_chunk[64];
__device__ unsigned int       g_thresh_bucket;
__device__ unsigned int       g_ncand;
__device__ unsigned long long g_cand[CAND_CAP];
__device__ int                g_top_idx[TOPK];
__device__ float              g_top_s[TOPK];
__device__ float              g_by1[TOPK], g_bx1[TOPK], g_by2[TOPK], g_bx2[TOPK], g_bar[TOPK];
__device__ unsigned int       g_mask[TOPK * NWORDS];   // 2MB suppression bitmask
__device__ int                g_out_pos[MAX_DET];
__device__ unsigned char      g_out_keep[MAX_DET];

// ---------------- helpers ----------------
__device__ __forceinline__ unsigned int f2key(float f) {
    unsigned int b = __float_as_uint(f);
    return b ^ ((b >> 31) ? 0xFFFFFFFFu : 0x80000000u);
}
__device__ __forceinline__ float key2f(unsigned int k) {
    unsigned int b = (k & 0x80000000u) ? (k ^ 0x80000000u) : ~k;
    return __uint_as_float(b);
}

// ---------------- k0: zero scratch (65536 threads) ----------------
__global__ void k_zero() {
    int i = blockIdx.x * blockDim.x + threadIdx.x;
    g_hist[i] = 0u;
#pragma unroll
    for (int k = 0; k < 8; k++) g_mask[k * 65536 + i] = 0u;   // 512K words
    if (i == 0) g_ncand = 0u;
}

// ---------------- k1: per-anchor score/class + histogram (warp per anchor) ---
__global__ void k_score(const float* __restrict__ x) {
    int warp = (blockIdx.x * blockDim.x + threadIdx.x) >> 5;
    int lane = threadIdx.x & 31;
    if (warp >= N_ANCH) return;
    const float* row = x + (size_t)warp * D_COLS;
    float obj = row[4];

    float best = -1.0f; int bc = NC;
#pragma unroll
    for (int k = 0; k < 3; k++) {
        int c = lane + 32 * k;
        if (c < NC) {
            float v = __fmul_rn(row[5 + c], obj);
            if (v > best) { best = v; bc = c; }
        }
    }
#pragma unroll
    for (int off = 16; off; off >>= 1) {
        float ov = __shfl_down_sync(0xFFFFFFFFu, best, off);
        int   oc = __shfl_down_sync(0xFFFFFFFFu, bc,   off);
        if (ov > best || (ov == best && oc < bc)) { best = ov; bc = oc; }
    }
    if (lane == 0) {
        float s = (obj > CONF_T) ? best : -1.0f;
        g_score[warp] = s;
        g_cls[warp]   = (float)bc;
        atomicAdd(&g_hist[f2key(s) >> 16], 1u);
    }
}

// ---------------- k2a: coalesced 1024-bucket chunk sums ----------------------
__global__ void k_chunk() {
    __shared__ unsigned int red[256];
    int b = blockIdx.x, t = threadIdx.x;
    unsigned int s = 0;
#pragma unroll
    for (int k = 0; k < 4; k++) s += g_hist[b * 1024 + k * 256 + t];
    red[t] = s;
    __syncthreads();
    for (int off = 128; off; off >>= 1) {
        if (t < off) red[t] += red[t + off];
        __syncthreads();
    }
    if (t == 0) g_chunk[b] = red[0];
}

// ---------------- k2b: threshold bucket -------------------------------------
__global__ void k_thresh2() {
    __shared__ unsigned int suf[1024];
    __shared__ unsigned int csum[64];
    __shared__ int          s_c;
    __shared__ unsigned int s_rem;
    int t = threadIdx.x;
    if (t < 64) csum[t] = g_chunk[t];
    __syncthreads();
    if (t == 0) {
        unsigned int cum = 0; int c = 0; unsigned int rem = TOPK;
        for (int b = 63; b >= 0; b--) {
            if (cum + csum[b] >= TOPK) { c = b; rem = TOPK - cum; break; }
            cum += csum[b];
        }
        s_c = c; s_rem = rem;
    }
    __syncthreads();
    int c = s_c;
    suf[t] = g_hist[c * 1024 + t];
    __syncthreads();
    for (int off = 1; off < 1024; off <<= 1) {
        unsigned int v = (t + off < 1024) ? suf[t + off] : 0u;
        __syncthreads();
        suf[t] += v;
        __syncthreads();
    }
    unsigned int rem = s_rem;
    if (suf[t] >= rem && (t == 1023 || suf[t + 1] < rem))
        g_thresh_bucket = (unsigned int)(c * 1024 + t);
}

// ---------------- k3: compact candidates ----------------
__global__ void k_compact() {
    int i = blockIdx.x * blockDim.x + threadIdx.x;
    if (i >= N_ANCH) return;
    unsigned int k = f2key(g_score[i]);
    if ((k >> 16) >= g_thresh_bucket) {
        unsigned int pos = atomicAdd(&g_ncand, 1u);
        if (pos < CAND_CAP)
            g_cand[pos] = ((unsigned long long)k << 32) | (unsigned int)(~i);
    }
}

// ---------------- k4: rank candidates -> sorted top-4096 ----------------
__global__ void k_rank() {
    __shared__ unsigned long long tile[256];
    int i = blockIdx.x * 256 + threadIdx.x;
    unsigned int n = g_ncand; if (n > CAND_CAP) n = CAND_CAP;
    unsigned long long my = (i < (int)n) ? g_cand[i] : 0ULL;
    int rank = 0;
    for (unsigned int base = 0; base < n; base += 256) {
        unsigned int idx = base + threadIdx.x;
        tile[threadIdx.x] = (idx < n) ? g_cand[idx] : 0ULL;
        __syncthreads();
        unsigned int lim = (n - base < 256u) ? (n - base) : 256u;
        for (unsigned int k = 0; k < lim; k++) rank += (tile[k] > my);
        __syncthreads();
    }
    if (i < (int)n && rank < TOPK) {
        g_top_s[rank]   = key2f((unsigned int)(my >> 32));
        g_top_idx[rank] = (int)(~(unsigned int)my);
    }
}

// ---------------- k5: gather boxes + areas of the top-4096 -------------------
__global__ void k_gather(const float* __restrict__ x) {
    int i = blockIdx.x * blockDim.x + threadIdx.x;
    if (i >= TOPK) return;
    const float* row = x + (size_t)g_top_idx[i] * D_COLS;
    float xc = row[0], yc = row[1], w = row[2], h = row[3];
    float hh = __fmul_rn(h, 0.5f), hw = __fmul_rn(w, 0.5f);
    float y1 = __fsub_rn(yc, hh), x1 = __fsub_rn(xc, hw);
    float y2 = __fadd_rn(yc, hh), x2 = __fadd_rn(xc, hw);
    g_by1[i] = y1; g_bx1[i] = x1; g_by2[i] = y2; g_bx2[i] = x2;
    g_bar[i] = __fmul_rn(__fsub_rn(y2, y1), __fsub_rn(x2, x1));
}

// ---------------- k6: dense suppression bitmask (chip-parallel, no atomics) --
// warp g: rows rg*32..+31 (lanes) vs cols w*32..+31 (loop) — upper triangle
__global__ void k_edges() {
    __shared__ float cy1[4][32], cx1[4][32], cy2[4][32], cx2[4][32], car[4][32];
    int wid  = threadIdx.x >> 5;
    int lane = threadIdx.x & 31;
    int g    = blockIdx.x * 4 + wid;
    int rg   = g >> 7;
    int w    = g & 127;
    if (w < rg) return;

    int jj = (w << 5) + lane;
    cy1[wid][lane] = g_by1[jj]; cx1[wid][lane] = g_bx1[jj];
    cy2[wid][lane] = g_by2[jj]; cx2[wid][lane] = g_bx2[jj];
    car[wid][lane] = g_bar[jj];
    __syncwarp();

    int   i   = (rg << 5) | lane;
    float ry1 = g_by1[i], rx1 = g_bx1[i], ry2 = g_by2[i], rx2 = g_bx2[i];
    float rar = g_bar[i];
    bool  diag = (w == rg);

    unsigned int word = 0;
#pragma unroll 4
    for (int k = 0; k < 32; k++) {
        if (diag && k <= lane) continue;
        float yy1 = fmaxf(ry1, cy1[wid][k]);
        float xx1 = fmaxf(rx1, cx1[wid][k]);
        float yy2 = fminf(ry2, cy2[wid][k]);
        float xx2 = fminf(rx2, cx2[wid][k]);
        float dh  = fmaxf(__fsub_rn(yy2, yy1), 0.0f);
        float dw  = fmaxf(__fsub_rn(xx2, xx1), 0.0f);
        float it  = __fmul_rn(dh, dw);
        if (it > 0.0f) {
            float un  = __fsub_rn(__fadd_rn(rar, car[wid][k]), it);
            float unc = fmaxf(un, 1e-9f);
            float c   = __fmul_rn(IOU_T, unc);
            bool  sup;
            if (fabsf(__fsub_rn(it, c)) > 1e-4f * c) {
                sup = (it > c);                       // far from boundary
            } else {
                sup = (__fdiv_rn(it, unc) > IOU_T);   // exact ref rounding
            }
            if (sup) word |= 1u << k;
        }
    }
    g_mask[i * NWORDS + w] = word;
}

// ---------------- k7: greedy sweep over bitmask (128 threads) ----------------
__global__ void __launch_bounds__(128, 1) k_resolve() {
    __shared__ unsigned int s_rm[NWORDS];
    __shared__ unsigned int s_kept;
    int t = threadIdx.x;

    // init removed word t from keep0 (score <= -0.5)
    unsigned int init_rm = 0;
#pragma unroll 4
    for (int b = 0; b < 32; b++)
        if (!(g_top_s[t * 32 + b] > -0.5f)) init_rm |= 1u << b;

    unsigned int acc = 0;   // OR of kept rows' masks, word t

    for (int w = 0; w < NWORDS; w++) {
        unsigned int rw[32];
#pragma unroll
        for (int b = 0; b < 32; b++)
            rw[b] = g_mask[(unsigned)((w << 5) + b) * NWORDS + t];

        if (t == w) {
            unsigned int rm = init_rm | acc;   // thread w owns word w
            unsigned int kept = 0;
#pragma unroll
            for (int b = 0; b < 32; b++) {
                if (!((rm >> b) & 1u)) { kept |= 1u << b; rm |= rw[b]; }
            }
            s_rm[w]  = rm;
            s_kept   = kept;
        }
        __syncthreads();
        unsigned int kept = s_kept;
#pragma unroll
        for (int b = 0; b < 32; b++)
            if ((kept >> b) & 1u) acc |= rw[b];
        __syncthreads();
    }

    if (t == 0) {                  // top-300 positions: kept first, then pad
        int cnt = 0;
        for (int w = 0; w < NWORDS && cnt < MAX_DET; w++) {
            unsigned int alive = ~s_rm[w];
            while (alive && cnt < MAX_DET) {
                int b = __ffs(alive) - 1; alive &= alive - 1;
                g_out_pos[cnt] = (w << 5) | b; g_out_keep[cnt] = 1; cnt++;
            }
        }
        for (int w = 0; w < NWORDS && cnt < MAX_DET; w++) {
            unsigned int dead = s_rm[w];
            while (dead && cnt < MAX_DET) {
                int b = __ffs(dead) - 1; dead &= dead - 1;
                g_out_pos[cnt] = (w << 5) | b; g_out_keep[cnt] = 0; cnt++;
            }
        }
    }
}

// ---------------- k8: final gather -> d_out (warp per detection) -------------
__global__ void k_out(const float* __restrict__ x, float* __restrict__ out) {
    int warp = (blockIdx.x * blockDim.x + threadIdx.x) >> 5;
    int lane = threadIdx.x & 31;
    if (warp >= MAX_DET) return;
    int pos = g_out_pos[warp];
    int a   = g_top_idx[pos];
    const float* row = x + (size_t)a * D_COLS;
    if (lane == 0) {
        float xc = row[0], yc = row[1], w = row[2], h = row[3];
        float hh = __fmul_rn(h, 0.5f), hw = __fmul_rn(w, 0.5f);
        out[warp * 4 + 0] = __fsub_rn(yc, hh);
        out[warp * 4 + 1] = __fsub_rn(xc, hw);
        out[warp * 4 + 2] = __fadd_rn(yc, hh);
        out[warp * 4 + 3] = __fadd_rn(xc, hw);
        out[MAX_DET * 4 + warp] = g_cls[a];
        out[MAX_DET * 5 + warp] = g_out_keep[warp] ? g_top_s[pos] : -1.0f;
    }
    out[MAX_DET * 6 + warp * NM + lane] = row[5 + NC + lane];
}

// ---------------- launch ----------------
extern "C" void kernel_launch(void* const* d_in, const int* in_sizes, int n_in,
                              void* d_out, int out_size) {
    const float* x = (const float*)d_in[0];
    float* out = (float*)d_out;

    k_zero    <<<64, 1024>>>();
    k_score   <<<(N_ANCH * 32 + 255) / 256, 256>>>(x);
    k_chunk   <<<64, 256>>>();
    k_thresh2 <<<1, 1024>>>();
    k_compact <<<(N_ANCH + 255) / 256, 256>>>();
    k_rank    <<<CAND_CAP / 256, 256>>>();
    k_gather  <<<TOPK / 256, 256>>>(x);
    k_edges   <<<4096, 128>>>();
    k_resolve <<<1, 128>>>();
    k_out     <<<(MAX_DET * 32 + 255) / 256, 256>>>(x, out);
}